// round 4
// baseline (speedup 1.0000x reference)
#include <cuda_runtime.h>
#include <cuda_bf16.h>
#include <cstddef>

#define COL    4096
#define TPB    256
#define WPB    (TPB/32)     // 8 warps per block, one row per warp
#define NCHUNK 16           // 16 chunks x 256 elements
#define F4C    64           // float4 per chunk

// Reciprocal table 1/(i+1), filled each launch (graph-capturable, no allocs).
__device__ float g_rinv[COL];

__global__ void rinv_init_kernel() {
    int i = blockIdx.x * blockDim.x + threadIdx.x;
    if (i < COL) g_rinv[i] = 1.0f / (float)(i + 1);
}

__global__ __launch_bounds__(TPB) void layernorm_v2_kernel(
    const float* __restrict__ x,
    const float* __restrict__ alpha,
    const float* __restrict__ beta,
    float* __restrict__ out)
{
    const int lane = threadIdx.x & 31;
    const int wid  = threadIdx.x >> 5;
    const size_t row = (size_t)blockIdx.x * WPB + wid;

    const float4* xr = (const float4*)(x + row * COL);
    const float4* rr = (const float4*)g_rinv;
    float4*       orw = (float4*)(out + row * COL);

    const int l2 = lane * 2;   // lane owns f4 indices c*64 + 2*lane, +1

    // ---- pass 1: sequential chunked scan + variance, double-buffered loads ----
    float4 c0 = xr[l2];
    float4 c1 = xr[l2 + 1];
    float carry = 0.0f;        // row prefix entering current chunk
    float acc   = 0.0f;        // variance accumulator

    #pragma unroll 1
    for (int c = 0; c < NCHUNK; ++c) {
        float4 n0, n1;
        if (c + 1 < NCHUNK) {                    // prefetch next chunk
            n0 = xr[(c + 1) * F4C + l2];
            n1 = xr[(c + 1) * F4C + l2 + 1];
        }
        const float4 r0 = rr[c * F4C + l2];      // L1-resident table
        const float4 r1 = rr[c * F4C + l2 + 1];

        // local inclusive scan of the 8-chunk
        const float p0 = c0.x;
        const float p1 = p0 + c0.y;
        const float p2 = p1 + c0.z;
        const float p3 = p2 + c0.w;
        const float p4 = p3 + c1.x;
        const float p5 = p4 + c1.y;
        const float p6 = p5 + c1.z;
        const float p7 = p6 + c1.w;
        const float tot = p7;

        // warp scan of lane totals
        float v = tot;
        #pragma unroll
        for (int o = 1; o < 32; o <<= 1) {
            float t = __shfl_up_sync(0xffffffffu, v, o);
            if (lane >= o) v += t;
        }
        const float chunk_total = __shfl_sync(0xffffffffu, v, 31);
        const float excl = carry + (v - tot);    // row-prefix before this lane's 8

        float d0 = c0.x - (excl + p0) * r0.x;
        float d1 = c0.y - (excl + p1) * r0.y;
        float d2 = c0.z - (excl + p2) * r0.z;
        float d3 = c0.w - (excl + p3) * r0.w;
        float d4 = c1.x - (excl + p4) * r1.x;
        float d5 = c1.y - (excl + p5) * r1.y;
        float d6 = c1.z - (excl + p6) * r1.z;
        float d7 = c1.w - (excl + p7) * r1.w;
        acc += ((d0 * d0 + d1 * d1) + (d2 * d2 + d3 * d3))
             + ((d4 * d4 + d5 * d5) + (d6 * d6 + d7 * d7));

        carry += chunk_total;
        c0 = n0;
        c1 = n1;
    }

    // ---- finish stats (warp-local, no barriers) ----
    #pragma unroll
    for (int o = 16; o > 0; o >>= 1) acc += __shfl_xor_sync(0xffffffffu, acc, o);

    const float var   = acc   * (1.0f / (float)(COL - 1));
    const float mean  = carry * (1.0f / (float)COL);
    const float scale = __ldg(alpha) * rsqrtf(var + 1e-5f);
    const float be    = __ldg(beta);

    // ---- pass 2: re-read row (L2 hit) and write normalized output ----
    #pragma unroll 4
    for (int c = 0; c < NCHUNK; ++c) {
        float4 a = xr[c * F4C + l2];
        float4 b = xr[c * F4C + l2 + 1];
        float4 oa, ob;
        oa.x = (a.x - mean) * scale + be;
        oa.y = (a.y - mean) * scale + be;
        oa.z = (a.z - mean) * scale + be;
        oa.w = (a.w - mean) * scale + be;
        ob.x = (b.x - mean) * scale + be;
        ob.y = (b.y - mean) * scale + be;
        ob.z = (b.z - mean) * scale + be;
        ob.w = (b.w - mean) * scale + be;
        orw[c * F4C + l2]     = oa;
        orw[c * F4C + l2 + 1] = ob;
    }
}

extern "C" void kernel_launch(void* const* d_in, const int* in_sizes, int n_in,
                              void* d_out, int out_size)
{
    const float* x     = (const float*)d_in[0];
    const float* alpha = (const float*)d_in[1];
    const float* beta  = (const float*)d_in[2];
    float*       out   = (float*)d_out;

    const int rows = in_sizes[0] / COL;
    const int grid = rows / WPB;                 // 4096 blocks x 8 warp-rows

    rinv_init_kernel<<<(COL + 255) / 256, 256>>>();
    layernorm_v2_kernel<<<grid, TPB>>>(x, alpha, beta, out);
}